// round 13
// baseline (speedup 1.0000x reference)
#include <cuda_runtime.h>
#include <cstdint>

// Problem constants
#define BB 256
#define SS 2048
#define TT 64
#define NCTA (BB / 2)          // 128 CTAs, 2 chains each
#define TILE 8                 // steps per feats tile (2 KB per chain)
#define NBUF 4
#define NTILES (SS / TILE)     // 256

// Partial results: [0..255] = fwd per batch, [256..511] = -gold per batch
__device__ float g_partial[2 * BB];

// ---------------- dtype detection helpers ----------------
__device__ __forceinline__ int detect_mask_kind(const void* m) {
    unsigned u = *reinterpret_cast<const unsigned*>(m);
    if (u == 0x3f800000u) return 2;      // float 1.0
    if (u == 1u)          return 1;      // int32 1
    return 0;                             // packed bool bytes
}
__device__ __forceinline__ int mask_nz(const void* m, int kind, size_t i) {
    if (kind == 0) return reinterpret_cast<const unsigned char*>(m)[i] != 0;
    if (kind == 1) return reinterpret_cast<const int*>(m)[i] != 0;
    return reinterpret_cast<const float*>(m)[i] != 0.0f;
}
__device__ __forceinline__ bool detect_tags64(const void* t) {
    const int* p = reinterpret_cast<const int*>(t);
    bool all_hi_zero = true;
#pragma unroll
    for (int k = 0; k < 8; k++)
        if (p[2 * k + 1] != 0) all_hi_zero = false;
    return all_hi_zero;
}
__device__ __forceinline__ int tag_at(const void* t, bool is64, size_t i) {
    if (is64) return (int)reinterpret_cast<const long long*>(t)[i];
    return reinterpret_cast<const int*>(t)[i];
}

// ---------------- packed f32x2 helpers ----------------
__device__ __forceinline__ void fma2(unsigned long long& d,
                                     unsigned long long a, unsigned long long b) {
    asm("fma.rn.f32x2 %0, %1, %2, %0;" : "+l"(d) : "l"(a), "l"(b));
}
__device__ __forceinline__ unsigned long long add2(unsigned long long a,
                                                   unsigned long long b) {
    unsigned long long d;
    asm("add.rn.f32x2 %0, %1, %2;" : "=l"(d) : "l"(a), "l"(b));
    return d;
}
__device__ __forceinline__ unsigned long long pk2(float x, float y) {
    unsigned long long d;
    asm("mov.b64 %0, {%1, %2};" : "=l"(d) : "r"(__float_as_uint(x)), "r"(__float_as_uint(y)));
    return d;
}
__device__ __forceinline__ float hadd2(unsigned long long a) {
    unsigned lo, hi;
    asm("mov.b64 {%0,%1}, %2;" : "=r"(lo), "=r"(hi) : "l"(a));
    return __uint_as_float(lo) + __uint_as_float(hi);
}

// ---------------- forward (log-partition) kernel ----------------
// ONE CTA (64 threads, 2 warps) owns TWO chains, processed back-to-back in
// the same instruction stream each round, then ONE __syncthreads:
//   - barrier amortized over 2 chain-steps
//   - the two matvecs are independent dep chains (ILP hides LDS latency)
//   - E = exp(trans) is batch-independent: shared registers for both chains
// Lane owns state j = tid for both chains (warp sw covers j in [32sw,32sw+32)).
// Linear-domain recurrence with lag-1 power-of-2 rescale (exact), per chain.
// feats staged via cp.async tiles (both chains' tile k in one commit group).
__global__ void __launch_bounds__(64)
crf_fwd_kernel(const float* __restrict__ feats,
               const float* __restrict__ trans,
               const float* __restrict__ startt,
               const float* __restrict__ endt,
               const void* __restrict__ mask) {
    __shared__ __align__(16) float sf[2][NBUF][TILE * TT];    // 16 KB
    __shared__ __align__(16) float wbuf[2][2][TT];            // 1 KB
    __shared__ float sscale[2][2];
    __shared__ float sred[2][2];

    const int tid = threadIdx.x;      // 0..63
    const int sw  = tid >> 5;
    const int l   = tid & 31;
    const int j   = tid;              // this lane's state (both chains)
    const int bA  = blockIdx.x * 2;
    const int bB  = bA + 1;
    const float* fbA = feats + (size_t)bA * SS * TT;
    const float* fbB = feats + (size_t)bB * SS * TT;

    // tile k for BOTH chains in one commit group (keeps R6's group counting)
    auto issue_tile = [&](int k) {
        if (k < NTILES) {
            const char* srcA = reinterpret_cast<const char*>(fbA)
                               + (size_t)k * TILE * TT * 4 + tid * 32;
            const char* srcB = reinterpret_cast<const char*>(fbB)
                               + (size_t)k * TILE * TT * 4 + tid * 32;
            unsigned dstA = (unsigned)__cvta_generic_to_shared(
                reinterpret_cast<char*>(&sf[0][k & (NBUF - 1)][0]) + tid * 32);
            unsigned dstB = (unsigned)__cvta_generic_to_shared(
                reinterpret_cast<char*>(&sf[1][k & (NBUF - 1)][0]) + tid * 32);
            asm volatile("cp.async.ca.shared.global [%0], [%1], 16;"
                         :: "r"(dstA), "l"(srcA));
            asm volatile("cp.async.ca.shared.global [%0], [%1], 16;"
                         :: "r"(dstA + 16), "l"(srcA + 16));
            asm volatile("cp.async.ca.shared.global [%0], [%1], 16;"
                         :: "r"(dstB), "l"(srcB));
            asm volatile("cp.async.ca.shared.global [%0], [%1], 16;"
                         :: "r"(dstB + 16), "l"(srcB + 16));
        }
        asm volatile("cp.async.commit_group;");
    };

    issue_tile(0);
    issue_tile(1);
    issue_tile(2);

    // ---- sequence lengths (mask is a prefix), warp-local ----
    const int mk = detect_mask_kind(mask);
    int LA, LB;
    {
        int ca = 0, cb = 0;
        const size_t baseA = (size_t)bA * SS;
        const size_t baseB = (size_t)bB * SS;
        for (int t = l; t < SS; t += 32) {
            ca += mask_nz(mask, mk, baseA + t);
            cb += mask_nz(mask, mk, baseB + t);
        }
#pragma unroll
        for (int o = 16; o; o >>= 1) {
            ca += __shfl_xor_sync(0xffffffffu, ca, o);
            cb += __shfl_xor_sync(0xffffffffu, cb, o);
        }
        LA = ca; LB = cb;
    }
    const int Lmax = (LA > LB) ? LA : LB;

    // ---- E column j in registers, packed over i-pairs (SHARED by chains) ----
    unsigned long long E[32];
#pragma unroll
    for (int k = 0; k < 32; k++) {
        float ea = trans[(2 * k) * TT + j];
        float eb = trans[(2 * k + 1) * TT + j];
        E[k] = pk2(__expf(ea), __expf(eb));
    }

    // ---- init w(0), sscale ----
    wbuf[0][0][j] = __expf(startt[j] + fbA[j]);
    wbuf[1][0][j] = __expf(startt[j] + fbB[j]);
    if (tid == 0) {
        sscale[0][0] = 1.0f; sscale[0][1] = 1.0f;
        sscale[1][0] = 1.0f; sscale[1][1] = 1.0f;
    }
    int eA = 0, LSA = 0, eB = 0, LSB = 0;   // meaningful on tid 0 only

    asm volatile("cp.async.wait_group 2;" ::: "memory");
    __syncthreads();

    // ---- main recurrence: one __syncthreads per round (= 2 chain-steps) ----
    for (int t = 1; t < Lmax; t++) {
        if ((t & (TILE - 1)) == 0) {
            int k = t >> 3;
            issue_tile(k + 2);
            asm volatile("cp.async.wait_group 2;" ::: "memory");
            __syncthreads();
        }

        const int rp = (t + 1) & 1, wp = t & 1;
        // lag-1 scales + emission factors (early loads)
        float scaleA = sscale[0][rp];
        float scaleB = sscale[1][rp];
        int foff = ((t & (TILE - 1)) << 6) + j;
        int fbuf = (t >> 3) & (NBUF - 1);
        float gA = __expf(sf[0][fbuf][foff]);
        float gB = __expf(sf[1][fbuf][foff]);

        // two independent matvecs, interleaved for ILP
        const ulonglong2* wa = reinterpret_cast<const ulonglong2*>(wbuf[0][rp]);
        const ulonglong2* wb = reinterpret_cast<const ulonglong2*>(wbuf[1][rp]);
        unsigned long long a0 = 0ull, a1 = 0ull, a2 = 0ull, a3 = 0ull;
        unsigned long long c0 = 0ull, c1 = 0ull, c2 = 0ull, c3 = 0ull;
#pragma unroll
        for (int q = 0; q < 8; q++) {
            ulonglong2 va1 = wa[2 * q];
            ulonglong2 vb1 = wb[2 * q];
            ulonglong2 va2 = wa[2 * q + 1];
            ulonglong2 vb2 = wb[2 * q + 1];
            fma2(a0, va1.x, E[4 * q + 0]);
            fma2(c0, vb1.x, E[4 * q + 0]);
            fma2(a1, va1.y, E[4 * q + 1]);
            fma2(c1, vb1.y, E[4 * q + 1]);
            fma2(a2, va2.x, E[4 * q + 2]);
            fma2(c2, vb2.x, E[4 * q + 2]);
            fma2(a3, va2.y, E[4 * q + 3]);
            fma2(c3, vb2.y, E[4 * q + 3]);
        }
        float sA = hadd2(add2(add2(a0, a1), add2(a2, a3)));
        float sB = hadd2(add2(add2(c0, c1), add2(c2, c3)));

        if (t < LA) wbuf[0][wp][j] = sA * (gA * scaleA);
        if (t < LB) wbuf[1][wp][j] = sB * (gB * scaleB);

        if (tid == 0) {                        // state-0 lane tracks scales
            if (t < LA) {
                LSA += eA;
                eA = ((__float_as_int(sA) >> 23) & 255) - 127;
                sscale[0][wp] = __int_as_float((127 - eA) << 23);
            }
            if (t < LB) {
                LSB += eB;
                eB = ((__float_as_int(sB) >> 23) & 255) - 127;
                sscale[1][wp] = __int_as_float((127 - eB) << 23);
            }
        }
        __syncthreads();
    }

    // ---- final logsumexp with end transitions (both chains) ----
    {
        float ee = __expf(endt[j]);
        float vA = wbuf[0][(LA - 1) & 1][j] * ee;
        float vB = wbuf[1][(LB - 1) & 1][j] * ee;
#pragma unroll
        for (int o = 16; o; o >>= 1) {
            vA += __shfl_down_sync(0xffffffffu, vA, o);
            vB += __shfl_down_sync(0xffffffffu, vB, o);
        }
        if (l == 0) { sred[0][sw] = vA; sred[1][sw] = vB; }
        __syncthreads();
        if (tid == 0) {
            g_partial[bA] = logf(sred[0][0] + sred[0][1])
                          + (float)LSA * 0.693147180559945309f;
            g_partial[bB] = logf(sred[1][0] + sred[1][1])
                          + (float)LSB * 0.693147180559945309f;
        }
    }
    asm volatile("cp.async.wait_group 0;" ::: "memory");
}

// ---------------- gold (path score) kernel ----------------
__global__ void __launch_bounds__(256)
crf_gold_kernel(const float* __restrict__ feats,
                const float* __restrict__ trans,
                const float* __restrict__ startt,
                const float* __restrict__ endt,
                const void* __restrict__ tags,
                const void* __restrict__ mask) {
    __shared__ float swr[8];
    __shared__ int   swc[8];

    const int b   = blockIdx.x;
    const int tid = threadIdx.x;
    const int mk  = detect_mask_kind(mask);
    const bool t64 = detect_tags64(tags);
    const size_t base = (size_t)b * SS;

    float acc = 0.f;
    int   cnt = 0;
    for (int t = tid; t < SS; t += 256) {
        int m0 = mask_nz(mask, mk, base + t);
        cnt += m0;
        if (t < SS - 1) {
            int tg  = tag_at(tags, t64, base + t);
            int tg1 = tag_at(tags, t64, base + t + 1);
            int m1  = mask_nz(mask, mk, base + t + 1);
            float em = feats[(base + (size_t)t) * TT + tg];
            float tr = trans[tg * TT + tg1];
            acc += tr * (float)m1 + em * (float)m0;
        }
    }
#pragma unroll
    for (int o = 16; o; o >>= 1) {
        acc += __shfl_down_sync(0xffffffffu, acc, o);
        cnt += __shfl_down_sync(0xffffffffu, cnt, o);
    }
    if ((tid & 31) == 0) { swr[tid >> 5] = acc; swc[tid >> 5] = cnt; }
    __syncthreads();
    if (tid == 0) {
        float a = 0.f; int L = 0;
#pragma unroll
        for (int ww = 0; ww < 8; ww++) { a += swr[ww]; L += swc[ww]; }
        int first = tag_at(tags, t64, base);
        int last  = tag_at(tags, t64, base + L - 1);
        float gold = a + startt[first] + endt[last];
        if (mask_nz(mask, mk, base + SS - 1))
            gold += feats[(base + (size_t)(SS - 1)) * TT + last];
        g_partial[BB + b] = -gold;
    }
}

// ---------------- deterministic final reduction ----------------
__global__ void __launch_bounds__(256)
crf_reduce_kernel(float* __restrict__ out) {
    __shared__ float sred[8];
    int tid = threadIdx.x;
    float v = g_partial[tid] + g_partial[tid + BB];
#pragma unroll
    for (int o = 16; o; o >>= 1) v += __shfl_down_sync(0xffffffffu, v, o);
    if ((tid & 31) == 0) sred[tid >> 5] = v;
    __syncthreads();
    if (tid == 0) {
        float tot = 0.f;
#pragma unroll
        for (int ww = 0; ww < 8; ww++) tot += sred[ww];
        out[0] = tot;
    }
}

extern "C" void kernel_launch(void* const* d_in, const int* in_sizes, int n_in,
                              void* d_out, int out_size) {
    const float* feats  = (const float*)d_in[0];
    const float* trans  = (const float*)d_in[1];
    const float* startt = (const float*)d_in[2];
    const float* endt   = (const float*)d_in[3];
    const void*  tags   = d_in[4];
    const void*  mask   = d_in[5];
    float* out = (float*)d_out;

    crf_fwd_kernel<<<NCTA, 64>>>(feats, trans, startt, endt, mask);
    crf_gold_kernel<<<BB, 256>>>(feats, trans, startt, endt, tags, mask);
    crf_reduce_kernel<<<1, 256>>>(out);
}

// round 14
// speedup vs baseline: 1.2546x; 1.2546x over previous
#include <cuda_runtime.h>
#include <cstdint>

// Problem constants
#define BB 256
#define SS 2048
#define TT 64
#define CH 2                   // chains per CTA (2 warps per chain)
#define NCTA (BB / CH)         // 128 fwd CTAs
#define TILE 16                // steps per feats tile (4 KB per chain)
#define NBUF 4
#define NTILES (SS / TILE)     // 128

// Partial results: [0..255] = fwd per batch, [256..511] = -gold per batch
__device__ float g_partial[2 * BB];

// ---------------- dtype detection helpers ----------------
__device__ __forceinline__ int detect_mask_kind(const void* m) {
    unsigned u = *reinterpret_cast<const unsigned*>(m);
    if (u == 0x3f800000u) return 2;      // float 1.0
    if (u == 1u)          return 1;      // int32 1
    return 0;                             // packed bool bytes
}
__device__ __forceinline__ int mask_nz(const void* m, int kind, size_t i) {
    if (kind == 0) return reinterpret_cast<const unsigned char*>(m)[i] != 0;
    if (kind == 1) return reinterpret_cast<const int*>(m)[i] != 0;
    return reinterpret_cast<const float*>(m)[i] != 0.0f;
}
__device__ __forceinline__ bool detect_tags64(const void* t) {
    const int* p = reinterpret_cast<const int*>(t);
    bool all_hi_zero = true;
#pragma unroll
    for (int k = 0; k < 8; k++)
        if (p[2 * k + 1] != 0) all_hi_zero = false;
    return all_hi_zero;
}
__device__ __forceinline__ int tag_at(const void* t, bool is64, size_t i) {
    if (is64) return (int)reinterpret_cast<const long long*>(t)[i];
    return reinterpret_cast<const int*>(t)[i];
}

// ---------------- packed f32x2 helpers ----------------
__device__ __forceinline__ void fma2(unsigned long long& d,
                                     unsigned long long a, unsigned long long b) {
    asm("fma.rn.f32x2 %0, %1, %2, %0;" : "+l"(d) : "l"(a), "l"(b));
}
__device__ __forceinline__ unsigned long long add2(unsigned long long a,
                                                   unsigned long long b) {
    unsigned long long d;
    asm("add.rn.f32x2 %0, %1, %2;" : "=l"(d) : "l"(a), "l"(b));
    return d;
}
__device__ __forceinline__ unsigned long long pk2(float x, float y) {
    unsigned long long d;
    asm("mov.b64 %0, {%1, %2};" : "=l"(d) : "r"(__float_as_uint(x)), "r"(__float_as_uint(y)));
    return d;
}
__device__ __forceinline__ float hadd2(unsigned long long a) {
    unsigned lo, hi;
    asm("mov.b64 {%0,%1}, %2;" : "=r"(lo), "=r"(hi) : "l"(a));
    return __uint_as_float(lo) + __uint_as_float(hi);
}

// ---------------- forward (log-partition) kernel ----------------
// R6 skeleton VERBATIM (2 chains/CTA, 2 warps/chain, 128 CTAs, 1 warp/SMSP,
// plain named bar.sync 64 per step, lag-1 power-of-2 rescale). Two mechanical
// trims only: TILE 16 (halves tile-maintenance frequency) and a 2x unrolled
// step loop with static buffer parities at the call sites.
__global__ void __launch_bounds__(128)
crf_fwd_kernel(const float* __restrict__ feats,
               const float* __restrict__ trans,
               const float* __restrict__ startt,
               const float* __restrict__ endt,
               const void* __restrict__ mask) {
    __shared__ __align__(16) float sf[CH][NBUF][TILE * TT];   // 32 KB
    __shared__ __align__(16) float wbuf[CH][2][TT];           // 1 KB
    __shared__ float sscale[CH][2];
    __shared__ float sred[CH][2];

    const int tid  = threadIdx.x;
    const int wid  = tid >> 5;
    const int l    = tid & 31;
    const int ch   = wid >> 1;         // chain within CTA
    const int sw   = wid & 1;          // sub-warp within chain
    const int wtid = (sw << 5) + l;    // 0..63 within chain
    const int b    = blockIdx.x * CH + ch;
    const int j    = (sw << 5) + l;    // this lane's state
    const int barid = 1 + ch;          // named barrier per chain
    const float* fb = feats + (size_t)b * SS * TT;

    auto chain_bar = [&]() {
        asm volatile("bar.sync %0, 64;" :: "r"(barid) : "memory");
    };

    // per-chain cp.async tile loader: tile k covers steps [k*TILE, (k+1)*TILE)
    auto issue_tile = [&](int k) {
        if (k < NTILES) {
            const char* src = reinterpret_cast<const char*>(fb)
                              + (size_t)k * TILE * TT * 4 + wtid * 64;
            unsigned dst = (unsigned)__cvta_generic_to_shared(
                reinterpret_cast<char*>(&sf[ch][k & (NBUF - 1)][0]) + wtid * 64);
#pragma unroll
            for (int c = 0; c < 4; c++)
                asm volatile("cp.async.ca.shared.global [%0], [%1], 16;"
                             :: "r"(dst + 16 * c), "l"(src + 16 * c));
        }
        asm volatile("cp.async.commit_group;");
    };

    issue_tile(0);
    issue_tile(1);
    issue_tile(2);

    // ---- sequence length (mask is a prefix), warp-local ----
    const int mk = detect_mask_kind(mask);
    int L;
    {
        int c = 0;
        const size_t base = (size_t)b * SS;
        for (int t = l; t < SS; t += 32) c += mask_nz(mask, mk, base + t);
#pragma unroll
        for (int o = 16; o; o >>= 1) c += __shfl_xor_sync(0xffffffffu, c, o);
        L = c;
    }

    // ---- E column j in registers, packed over i-pairs ----
    unsigned long long E[32];
#pragma unroll
    for (int k = 0; k < 32; k++) {
        float ea = trans[(2 * k) * TT + j];
        float eb = trans[(2 * k + 1) * TT + j];
        E[k] = pk2(__expf(ea), __expf(eb));
    }

    // ---- init w(0), sscale ----
    wbuf[ch][0][j] = __expf(startt[j] + fb[j]);
    if (wtid == 0) { sscale[ch][0] = 1.0f; sscale[ch][1] = 1.0f; }
    int e_cur = 0, LS = 0;     // meaningful on the state-0 lane only

    asm volatile("cp.async.wait_group 2;" ::: "memory");
    chain_bar();

    // one recurrence step; sp = t&1 is a compile-time literal at call sites
    auto stepfn = [&](int t, const float* rb, float* wb, int sp) {
        // lag-1 scale (posted at step t-1) + emission factor (early loads)
        float scale = sscale[ch][sp ^ 1];
        float fg = sf[ch][(t >> 4) & (NBUF - 1)][((t & (TILE - 1)) << 6) + j];
        float g = exp2f(fg * 1.44269504f);

        // row j of the matvec: 32 packed FMA2 over broadcast w (16 LDS.128)
        const ulonglong2* wv = reinterpret_cast<const ulonglong2*>(rb);
        unsigned long long a0 = 0ull, a1 = 0ull, a2 = 0ull, a3 = 0ull;
#pragma unroll
        for (int q = 0; q < 8; q++) {
            ulonglong2 v1 = wv[2 * q];
            ulonglong2 v2 = wv[2 * q + 1];
            fma2(a0, v1.x, E[4 * q + 0]);
            fma2(a1, v1.y, E[4 * q + 1]);
            fma2(a2, v2.x, E[4 * q + 2]);
            fma2(a3, v2.y, E[4 * q + 3]);
        }
        float s = hadd2(add2(add2(a0, a1), add2(a2, a3)));

        wb[j] = s * (g * scale);

        // scale-exponent tracker: state 0 lives on warp0-lane0; lag-1 post
        if (wtid == 0) {
            LS += e_cur;
            e_cur = ((__float_as_int(s) >> 23) & 255) - 127;
            sscale[ch][sp] = __int_as_float((127 - e_cur) << 23);
        }
        chain_bar();
    };

    // ---- main recurrence, 2x unrolled; tile edges (mult of 16) are even ----
    float* w0 = wbuf[ch][0];
    float* w1 = wbuf[ch][1];
    int t = 1;
    for (; t + 1 < L; t += 2) {
        stepfn(t, w0, w1, 1);                   // t odd: never a tile edge
        int tn = t + 1;
        if ((tn & (TILE - 1)) == 0) {
            int k = tn >> 4;
            issue_tile(k + 2);
            asm volatile("cp.async.wait_group 2;" ::: "memory");
            chain_bar();
        }
        stepfn(tn, w1, w0, 0);
    }
    if (t < L) stepfn(t, w0, w1, 1);

    // ---- final logsumexp with end transitions ----
    {
        float v = wbuf[ch][(L - 1) & 1][j] * __expf(endt[j]);
#pragma unroll
        for (int o = 16; o; o >>= 1) v += __shfl_down_sync(0xffffffffu, v, o);
        if (l == 0) sred[ch][sw] = v;
        chain_bar();
        if (wtid == 0)
            g_partial[b] = logf(sred[ch][0] + sred[ch][1])
                         + (float)LS * 0.693147180559945309f;
    }
    asm volatile("cp.async.wait_group 0;" ::: "memory");
}

// ---------------- gold (path score) kernel ----------------
__global__ void __launch_bounds__(256)
crf_gold_kernel(const float* __restrict__ feats,
                const float* __restrict__ trans,
                const float* __restrict__ startt,
                const float* __restrict__ endt,
                const void* __restrict__ tags,
                const void* __restrict__ mask) {
    __shared__ float swr[8];
    __shared__ int   swc[8];

    const int b   = blockIdx.x;
    const int tid = threadIdx.x;
    const int mk  = detect_mask_kind(mask);
    const bool t64 = detect_tags64(tags);
    const size_t base = (size_t)b * SS;

    float acc = 0.f;
    int   cnt = 0;
    for (int t = tid; t < SS; t += 256) {
        int m0 = mask_nz(mask, mk, base + t);
        cnt += m0;
        if (t < SS - 1) {
            int tg  = tag_at(tags, t64, base + t);
            int tg1 = tag_at(tags, t64, base + t + 1);
            int m1  = mask_nz(mask, mk, base + t + 1);
            float em = feats[(base + (size_t)t) * TT + tg];
            float tr = trans[tg * TT + tg1];
            acc += tr * (float)m1 + em * (float)m0;
        }
    }
#pragma unroll
    for (int o = 16; o; o >>= 1) {
        acc += __shfl_down_sync(0xffffffffu, acc, o);
        cnt += __shfl_down_sync(0xffffffffu, cnt, o);
    }
    if ((tid & 31) == 0) { swr[tid >> 5] = acc; swc[tid >> 5] = cnt; }
    __syncthreads();
    if (tid == 0) {
        float a = 0.f; int L = 0;
#pragma unroll
        for (int ww = 0; ww < 8; ww++) { a += swr[ww]; L += swc[ww]; }
        int first = tag_at(tags, t64, base);
        int last  = tag_at(tags, t64, base + L - 1);
        float gold = a + startt[first] + endt[last];
        if (mask_nz(mask, mk, base + SS - 1))
            gold += feats[(base + (size_t)(SS - 1)) * TT + last];
        g_partial[BB + b] = -gold;
    }
}

// ---------------- deterministic final reduction ----------------
__global__ void __launch_bounds__(256)
crf_reduce_kernel(float* __restrict__ out) {
    __shared__ float sred[8];
    int tid = threadIdx.x;
    float v = g_partial[tid] + g_partial[tid + BB];
#pragma unroll
    for (int o = 16; o; o >>= 1) v += __shfl_down_sync(0xffffffffu, v, o);
    if ((tid & 31) == 0) sred[tid >> 5] = v;
    __syncthreads();
    if (tid == 0) {
        float tot = 0.f;
#pragma unroll
        for (int ww = 0; ww < 8; ww++) tot += sred[ww];
        out[0] = tot;
    }
}

extern "C" void kernel_launch(void* const* d_in, const int* in_sizes, int n_in,
                              void* d_out, int out_size) {
    const float* feats  = (const float*)d_in[0];
    const float* trans  = (const float*)d_in[1];
    const float* startt = (const float*)d_in[2];
    const float* endt   = (const float*)d_in[3];
    const void*  tags   = d_in[4];
    const void*  mask   = d_in[5];
    float* out = (float*)d_out;

    crf_fwd_kernel<<<NCTA, 128>>>(feats, trans, startt, endt, mask);
    crf_gold_kernel<<<BB, 256>>>(feats, trans, startt, endt, tags, mask);
    crf_reduce_kernel<<<1, 256>>>(out);
}

// round 15
// speedup vs baseline: 2.3967x; 1.9102x over previous
#include <cuda_runtime.h>
#include <cstdint>

// Problem constants
#define BB 256
#define SS 2048
#define TT 64
#define CH 2                   // chains per CTA (2 warps per chain)
#define NCTA (BB / CH)         // 128 fwd CTAs
#define TILE 8                 // steps per feats tile (2 KB per chain)
#define NBUF 4
#define NTILES (SS / TILE)     // 256

// Partial results: [0..255] = fwd per batch, [256..511] = -gold per batch
__device__ float g_partial[2 * BB];

// ---------------- dtype detection helpers ----------------
__device__ __forceinline__ int detect_mask_kind(const void* m) {
    unsigned u = *reinterpret_cast<const unsigned*>(m);
    if (u == 0x3f800000u) return 2;      // float 1.0
    if (u == 1u)          return 1;      // int32 1
    return 0;                             // packed bool bytes
}
__device__ __forceinline__ int mask_nz(const void* m, int kind, size_t i) {
    if (kind == 0) return reinterpret_cast<const unsigned char*>(m)[i] != 0;
    if (kind == 1) return reinterpret_cast<const int*>(m)[i] != 0;
    return reinterpret_cast<const float*>(m)[i] != 0.0f;
}
__device__ __forceinline__ bool detect_tags64(const void* t) {
    const int* p = reinterpret_cast<const int*>(t);
    bool all_hi_zero = true;
#pragma unroll
    for (int k = 0; k < 8; k++)
        if (p[2 * k + 1] != 0) all_hi_zero = false;
    return all_hi_zero;
}
__device__ __forceinline__ int tag_at(const void* t, bool is64, size_t i) {
    if (is64) return (int)reinterpret_cast<const long long*>(t)[i];
    return reinterpret_cast<const int*>(t)[i];
}

// ---------------- packed f32x2 helpers ----------------
__device__ __forceinline__ void fma2(unsigned long long& d,
                                     unsigned long long a, unsigned long long b) {
    asm("fma.rn.f32x2 %0, %1, %2, %0;" : "+l"(d) : "l"(a), "l"(b));
}
__device__ __forceinline__ unsigned long long add2(unsigned long long a,
                                                   unsigned long long b) {
    unsigned long long d;
    asm("add.rn.f32x2 %0, %1, %2;" : "=l"(d) : "l"(a), "l"(b));
    return d;
}
__device__ __forceinline__ unsigned long long pk2(float x, float y) {
    unsigned long long d;
    asm("mov.b64 %0, {%1, %2};" : "=l"(d) : "r"(__float_as_uint(x)), "r"(__float_as_uint(y)));
    return d;
}
__device__ __forceinline__ float hadd2(unsigned long long a) {
    unsigned lo, hi;
    asm("mov.b64 {%0,%1}, %2;" : "=r"(lo), "=r"(hi) : "l"(a));
    return __uint_as_float(lo) + __uint_as_float(hi);
}

// ---------------- forward (log-partition) kernel ----------------
// R6 skeleton (2 chains/CTA, 2 warps/chain, 128 CTAs, 1 warp/SMSP, plain
// named bar.sync 64 per step, TILE 8 cp.async pipeline, single-copy loop
// body). ONE change vs R6: the power-of-2 rescale is register-resident and
// symmetric — each lane derives scale_t = 2^-e(w_{t-1}[0]) from the first
// LDS.128 it already performs (wv[0].x low word), and accumulates LS
// locally. Removes the sscale smem array, its critical-path LDS, and the
// warp-0-only predicated tail that delayed warp 0's barrier arrival.
__global__ void __launch_bounds__(128)
crf_fwd_kernel(const float* __restrict__ feats,
               const float* __restrict__ trans,
               const float* __restrict__ startt,
               const float* __restrict__ endt,
               const void* __restrict__ mask) {
    __shared__ __align__(16) float sf[CH][NBUF][TILE * TT];   // 16 KB
    __shared__ __align__(16) float wbuf[CH][2][TT];           // 1 KB
    __shared__ float sred[CH][2];

    const int tid  = threadIdx.x;
    const int wid  = tid >> 5;
    const int l    = tid & 31;
    const int ch   = wid >> 1;         // chain within CTA
    const int sw   = wid & 1;          // sub-warp within chain
    const int wtid = (sw << 5) + l;    // 0..63 within chain
    const int b    = blockIdx.x * CH + ch;
    const int j    = (sw << 5) + l;    // this lane's state
    const int barid = 1 + ch;          // named barrier per chain
    const float* fb = feats + (size_t)b * SS * TT;

    auto chain_bar = [&]() {
        asm volatile("bar.sync %0, 64;" :: "r"(barid) : "memory");
    };

    // per-chain cp.async tile loader: tile k covers steps [k*TILE, k*TILE+TILE)
    auto issue_tile = [&](int k) {
        if (k < NTILES) {
            const char* src = reinterpret_cast<const char*>(fb)
                              + (size_t)k * TILE * TT * 4 + wtid * 32;
            unsigned dst = (unsigned)__cvta_generic_to_shared(
                reinterpret_cast<char*>(&sf[ch][k & (NBUF - 1)][0]) + wtid * 32);
            asm volatile("cp.async.ca.shared.global [%0], [%1], 16;"
                         :: "r"(dst), "l"(src));
            asm volatile("cp.async.ca.shared.global [%0], [%1], 16;"
                         :: "r"(dst + 16), "l"(src + 16));
        }
        asm volatile("cp.async.commit_group;");
    };

    issue_tile(0);
    issue_tile(1);
    issue_tile(2);

    // ---- sequence length (mask is a prefix), warp-local ----
    const int mk = detect_mask_kind(mask);
    int L;
    {
        int c = 0;
        const size_t base = (size_t)b * SS;
        for (int t = l; t < SS; t += 32) c += mask_nz(mask, mk, base + t);
#pragma unroll
        for (int o = 16; o; o >>= 1) c += __shfl_xor_sync(0xffffffffu, c, o);
        L = c;
    }

    // ---- E column j in registers, packed over i-pairs ----
    unsigned long long E[32];
#pragma unroll
    for (int k = 0; k < 32; k++) {
        float ea = trans[(2 * k) * TT + j];
        float eb = trans[(2 * k + 1) * TT + j];
        E[k] = pk2(__expf(ea), __expf(eb));
    }

    // ---- init w(0) ----
    wbuf[ch][0][j] = __expf(startt[j] + fb[j]);
    int LS = 0;                // accumulated rescale exponent (all lanes equal)

    asm volatile("cp.async.wait_group 2;" ::: "memory");
    chain_bar();

    // ---- main recurrence: one named barrier per step ----
    for (int t = 1; t < L; t++) {
        if ((t & (TILE - 1)) == 0) {
            int k = t >> 3;
            issue_tile(k + 2);
            asm volatile("cp.async.wait_group 2;" ::: "memory");
            chain_bar();
        }

        // emission factor (early load)
        float fg = sf[ch][(t >> 3) & (NBUF - 1)][((t & (TILE - 1)) << 6) + j];
        float g = exp2f(fg * 1.44269504f);

        // row j of the matvec: 32 packed FMA2 over broadcast w (16 LDS.128)
        const ulonglong2* wv =
            reinterpret_cast<const ulonglong2*>(wbuf[ch][(t + 1) & 1]);
        unsigned long long a0 = 0ull, a1 = 0ull, a2 = 0ull, a3 = 0ull;

        // first vector load carries w_prev[0] in the low word of v1.x:
        // derive this step's uniform power-of-2 rescale from its exponent
        // (off the critical path; identical in every lane of both warps).
        ulonglong2 v1_0 = wv[0];
        ulonglong2 v2_0 = wv[1];
        unsigned w0bits = (unsigned)v1_0.x;
        int ebias = (int)((w0bits >> 23) & 255);
        LS += ebias - 127;
        float scale = __int_as_float((254 - ebias) << 23);   // 2^{127-ebias}
        fma2(a0, v1_0.x, E[0]);
        fma2(a1, v1_0.y, E[1]);
        fma2(a2, v2_0.x, E[2]);
        fma2(a3, v2_0.y, E[3]);
#pragma unroll
        for (int q = 1; q < 8; q++) {
            ulonglong2 v1 = wv[2 * q];
            ulonglong2 v2 = wv[2 * q + 1];
            fma2(a0, v1.x, E[4 * q + 0]);
            fma2(a1, v1.y, E[4 * q + 1]);
            fma2(a2, v2.x, E[4 * q + 2]);
            fma2(a3, v2.y, E[4 * q + 3]);
        }
        float s = hadd2(add2(add2(a0, a1), add2(a2, a3)));

        wbuf[ch][t & 1][j] = s * (g * scale);
        chain_bar();
    }

    // ---- final logsumexp with end transitions ----
    {
        float v = wbuf[ch][(L - 1) & 1][j] * __expf(endt[j]);
#pragma unroll
        for (int o = 16; o; o >>= 1) v += __shfl_down_sync(0xffffffffu, v, o);
        if (l == 0) sred[ch][sw] = v;
        chain_bar();
        if (wtid == 0)
            g_partial[b] = logf(sred[ch][0] + sred[ch][1])
                         + (float)LS * 0.693147180559945309f;
    }
    asm volatile("cp.async.wait_group 0;" ::: "memory");
}

// ---------------- gold (path score) kernel ----------------
__global__ void __launch_bounds__(256)
crf_gold_kernel(const float* __restrict__ feats,
                const float* __restrict__ trans,
                const float* __restrict__ startt,
                const float* __restrict__ endt,
                const void* __restrict__ tags,
                const void* __restrict__ mask) {
    __shared__ float swr[8];
    __shared__ int   swc[8];

    const int b   = blockIdx.x;
    const int tid = threadIdx.x;
    const int mk  = detect_mask_kind(mask);
    const bool t64 = detect_tags64(tags);
    const size_t base = (size_t)b * SS;

    float acc = 0.f;
    int   cnt = 0;
    for (int t = tid; t < SS; t += 256) {
        int m0 = mask_nz(mask, mk, base + t);
        cnt += m0;
        if (t < SS - 1) {
            int tg  = tag_at(tags, t64, base + t);
            int tg1 = tag_at(tags, t64, base + t + 1);
            int m1  = mask_nz(mask, mk, base + t + 1);
            float em = feats[(base + (size_t)t) * TT + tg];
            float tr = trans[tg * TT + tg1];
            acc += tr * (float)m1 + em * (float)m0;
        }
    }
#pragma unroll
    for (int o = 16; o; o >>= 1) {
        acc += __shfl_down_sync(0xffffffffu, acc, o);
        cnt += __shfl_down_sync(0xffffffffu, cnt, o);
    }
    if ((tid & 31) == 0) { swr[tid >> 5] = acc; swc[tid >> 5] = cnt; }
    __syncthreads();
    if (tid == 0) {
        float a = 0.f; int L = 0;
#pragma unroll
        for (int ww = 0; ww < 8; ww++) { a += swr[ww]; L += swc[ww]; }
        int first = tag_at(tags, t64, base);
        int last  = tag_at(tags, t64, base + L - 1);
        float gold = a + startt[first] + endt[last];
        if (mask_nz(mask, mk, base + SS - 1))
            gold += feats[(base + (size_t)(SS - 1)) * TT + last];
        g_partial[BB + b] = -gold;
    }
}

// ---------------- deterministic final reduction ----------------
__global__ void __launch_bounds__(256)
crf_reduce_kernel(float* __restrict__ out) {
    __shared__ float sred[8];
    int tid = threadIdx.x;
    float v = g_partial[tid] + g_partial[tid + BB];
#pragma unroll
    for (int o = 16; o; o >>= 1) v += __shfl_down_sync(0xffffffffu, v, o);
    if ((tid & 31) == 0) sred[tid >> 5] = v;
    __syncthreads();
    if (tid == 0) {
        float tot = 0.f;
#pragma unroll
        for (int ww = 0; ww < 8; ww++) tot += sred[ww];
        out[0] = tot;
    }
}

extern "C" void kernel_launch(void* const* d_in, const int* in_sizes, int n_in,
                              void* d_out, int out_size) {
    const float* feats  = (const float*)d_in[0];
    const float* trans  = (const float*)d_in[1];
    const float* startt = (const float*)d_in[2];
    const float* endt   = (const float*)d_in[3];
    const void*  tags   = d_in[4];
    const void*  mask   = d_in[5];
    float* out = (float*)d_out;

    crf_fwd_kernel<<<NCTA, 128>>>(feats, trans, startt, endt, mask);
    crf_gold_kernel<<<BB, 256>>>(feats, trans, startt, endt, tags, mask);
    crf_reduce_kernel<<<1, 256>>>(out);
}

// round 16
// speedup vs baseline: 2.4477x; 1.0213x over previous
#include <cuda_runtime.h>
#include <cstdint>

// Problem constants
#define BB 256
#define SS 2048
#define TT 64
#define CH 2                   // chains per CTA (2 warps per chain)
#define NCTA (BB / CH)         // 128 fwd CTAs
#define TILE 8                 // steps per feats tile (2 KB per chain)
#define NBUF 4
#define NTILES (SS / TILE)     // 256

// Partial results: [0..255] = fwd per batch, [256..511] = -gold per batch
__device__ float g_partial[2 * BB];
__device__ int   g_ticket = 0;     // last-block-done ticket (self-resetting)

// ---------------- dtype detection helpers ----------------
__device__ __forceinline__ int detect_mask_kind(const void* m) {
    unsigned u = *reinterpret_cast<const unsigned*>(m);
    if (u == 0x3f800000u) return 2;      // float 1.0
    if (u == 1u)          return 1;      // int32 1
    return 0;                             // packed bool bytes
}
__device__ __forceinline__ int mask_nz(const void* m, int kind, size_t i) {
    if (kind == 0) return reinterpret_cast<const unsigned char*>(m)[i] != 0;
    if (kind == 1) return reinterpret_cast<const int*>(m)[i] != 0;
    return reinterpret_cast<const float*>(m)[i] != 0.0f;
}
__device__ __forceinline__ bool detect_tags64(const void* t) {
    const int* p = reinterpret_cast<const int*>(t);
    bool all_hi_zero = true;
#pragma unroll
    for (int k = 0; k < 8; k++)
        if (p[2 * k + 1] != 0) all_hi_zero = false;
    return all_hi_zero;
}
__device__ __forceinline__ int tag_at(const void* t, bool is64, size_t i) {
    if (is64) return (int)reinterpret_cast<const long long*>(t)[i];
    return reinterpret_cast<const int*>(t)[i];
}

// ---------------- packed f32x2 helpers ----------------
__device__ __forceinline__ void fma2(unsigned long long& d,
                                     unsigned long long a, unsigned long long b) {
    asm("fma.rn.f32x2 %0, %1, %2, %0;" : "+l"(d) : "l"(a), "l"(b));
}
__device__ __forceinline__ unsigned long long add2(unsigned long long a,
                                                   unsigned long long b) {
    unsigned long long d;
    asm("add.rn.f32x2 %0, %1, %2;" : "=l"(d) : "l"(a), "l"(b));
    return d;
}
__device__ __forceinline__ unsigned long long pk2(float x, float y) {
    unsigned long long d;
    asm("mov.b64 %0, {%1, %2};" : "=l"(d) : "r"(__float_as_uint(x)), "r"(__float_as_uint(y)));
    return d;
}
__device__ __forceinline__ float hadd2(unsigned long long a) {
    unsigned lo, hi;
    asm("mov.b64 {%0,%1}, %2;" : "=r"(lo), "=r"(hi) : "l"(a));
    return __uint_as_float(lo) + __uint_as_float(hi);
}

// ---------------- forward (log-partition) kernel — R6 CHAMPION, VERBATIM ----
__global__ void __launch_bounds__(128)
crf_fwd_kernel(const float* __restrict__ feats,
               const float* __restrict__ trans,
               const float* __restrict__ startt,
               const float* __restrict__ endt,
               const void* __restrict__ mask) {
    __shared__ __align__(16) float sf[CH][NBUF][TILE * TT];   // 16 KB
    __shared__ __align__(16) float wbuf[CH][2][TT];           // 1 KB
    __shared__ float sscale[CH][2];
    __shared__ float sred[CH][2];

    const int tid  = threadIdx.x;
    const int wid  = tid >> 5;
    const int l    = tid & 31;
    const int ch   = wid >> 1;         // chain within CTA
    const int sw   = wid & 1;          // sub-warp within chain
    const int wtid = (sw << 5) + l;    // 0..63 within chain
    const int b    = blockIdx.x * CH + ch;
    const int j    = (sw << 5) + l;    // this lane's state
    const int barid = 1 + ch;          // named barrier per chain
    const float* fb = feats + (size_t)b * SS * TT;

    auto chain_bar = [&]() {
        asm volatile("bar.sync %0, 64;" :: "r"(barid) : "memory");
    };

    // per-chain cp.async tile loader: tile k covers steps [k*TILE, k*TILE+TILE)
    auto issue_tile = [&](int k) {
        if (k < NTILES) {
            const char* src = reinterpret_cast<const char*>(fb)
                              + (size_t)k * TILE * TT * 4 + wtid * 32;
            unsigned dst = (unsigned)__cvta_generic_to_shared(
                reinterpret_cast<char*>(&sf[ch][k & (NBUF - 1)][0]) + wtid * 32);
            asm volatile("cp.async.ca.shared.global [%0], [%1], 16;"
                         :: "r"(dst), "l"(src));
            asm volatile("cp.async.ca.shared.global [%0], [%1], 16;"
                         :: "r"(dst + 16), "l"(src + 16));
        }
        asm volatile("cp.async.commit_group;");
    };

    issue_tile(0);
    issue_tile(1);
    issue_tile(2);

    // ---- sequence length (mask is a prefix), warp-local ----
    const int mk = detect_mask_kind(mask);
    int L;
    {
        int c = 0;
        const size_t base = (size_t)b * SS;
        for (int t = l; t < SS; t += 32) c += mask_nz(mask, mk, base + t);
#pragma unroll
        for (int o = 16; o; o >>= 1) c += __shfl_xor_sync(0xffffffffu, c, o);
        L = c;
    }

    // ---- E column j in registers, packed over i-pairs ----
    unsigned long long E[32];
#pragma unroll
    for (int k = 0; k < 32; k++) {
        float ea = trans[(2 * k) * TT + j];
        float eb = trans[(2 * k + 1) * TT + j];
        E[k] = pk2(__expf(ea), __expf(eb));
    }

    // ---- init w(0), sscale ----
    wbuf[ch][0][j] = __expf(startt[j] + fb[j]);
    if (wtid == 0) { sscale[ch][0] = 1.0f; sscale[ch][1] = 1.0f; }
    int e_cur = 0, LS = 0;     // meaningful on the state-0 lane only

    asm volatile("cp.async.wait_group 2;" ::: "memory");
    chain_bar();

    // ---- main recurrence: one named barrier per step ----
    for (int t = 1; t < L; t++) {
        if ((t & (TILE - 1)) == 0) {
            int k = t >> 3;
            issue_tile(k + 2);
            asm volatile("cp.async.wait_group 2;" ::: "memory");
            chain_bar();
        }

        // lag-1 scale (posted at step t-1) + emission factor (early loads)
        float scale = sscale[ch][(t + 1) & 1];
        float fg = sf[ch][(t >> 3) & (NBUF - 1)][((t & (TILE - 1)) << 6) + j];
        float g = exp2f(fg * 1.44269504f);

        // row j of the matvec: 32 packed FMA2 over broadcast w (16 LDS.128)
        const ulonglong2* wv =
            reinterpret_cast<const ulonglong2*>(wbuf[ch][(t + 1) & 1]);
        unsigned long long a0 = 0ull, a1 = 0ull, a2 = 0ull, a3 = 0ull;
#pragma unroll
        for (int q = 0; q < 8; q++) {
            ulonglong2 v1 = wv[2 * q];
            ulonglong2 v2 = wv[2 * q + 1];
            fma2(a0, v1.x, E[4 * q + 0]);
            fma2(a1, v1.y, E[4 * q + 1]);
            fma2(a2, v2.x, E[4 * q + 2]);
            fma2(a3, v2.y, E[4 * q + 3]);
        }
        float s = hadd2(add2(add2(a0, a1), add2(a2, a3)));

        wbuf[ch][t & 1][j] = s * (g * scale);

        // scale-exponent tracker: state 0 lives on warp0-lane0; lag-1 post
        if (wtid == 0) {
            LS += e_cur;
            e_cur = ((__float_as_int(s) >> 23) & 255) - 127;
            sscale[ch][t & 1] = __int_as_float((127 - e_cur) << 23);
        }
        chain_bar();
    }

    // ---- final logsumexp with end transitions ----
    {
        float v = wbuf[ch][(L - 1) & 1][j] * __expf(endt[j]);
#pragma unroll
        for (int o = 16; o; o >>= 1) v += __shfl_down_sync(0xffffffffu, v, o);
        if (l == 0) sred[ch][sw] = v;
        chain_bar();
        if (wtid == 0)
            g_partial[b] = logf(sred[ch][0] + sred[ch][1])
                         + (float)LS * 0.693147180559945309f;
    }
    asm volatile("cp.async.wait_group 0;" ::: "memory");
}

// ---------------- gold (path score) kernel + folded final reduction ----------
// 512 threads per CTA (halves the per-thread gather depth vs 256).
// The LAST CTA to finish (threadfence + ticket) performs the deterministic
// fixed-order 512-value reduction and writes out[0] — removes the separate
// reduce launch. Winner resets the ticket for graph replays.
__global__ void __launch_bounds__(512)
crf_gold_kernel(const float* __restrict__ feats,
                const float* __restrict__ trans,
                const float* __restrict__ startt,
                const float* __restrict__ endt,
                const void* __restrict__ tags,
                const void* __restrict__ mask,
                float* __restrict__ out) {
    __shared__ float swr[16];
    __shared__ int   swc[16];
    __shared__ int   s_last;

    const int b   = blockIdx.x;
    const int tid = threadIdx.x;
    const int mk  = detect_mask_kind(mask);
    const bool t64 = detect_tags64(tags);
    const size_t base = (size_t)b * SS;

    float acc = 0.f;
    int   cnt = 0;
    for (int t = tid; t < SS; t += 512) {
        int m0 = mask_nz(mask, mk, base + t);
        cnt += m0;
        if (t < SS - 1) {
            int tg  = tag_at(tags, t64, base + t);
            int tg1 = tag_at(tags, t64, base + t + 1);
            int m1  = mask_nz(mask, mk, base + t + 1);
            float em = feats[(base + (size_t)t) * TT + tg];
            float tr = trans[tg * TT + tg1];
            acc += tr * (float)m1 + em * (float)m0;
        }
    }
#pragma unroll
    for (int o = 16; o; o >>= 1) {
        acc += __shfl_down_sync(0xffffffffu, acc, o);
        cnt += __shfl_down_sync(0xffffffffu, cnt, o);
    }
    if ((tid & 31) == 0) { swr[tid >> 5] = acc; swc[tid >> 5] = cnt; }
    __syncthreads();
    if (tid == 0) {
        float a = 0.f; int L = 0;
#pragma unroll
        for (int ww = 0; ww < 16; ww++) { a += swr[ww]; L += swc[ww]; }
        int first = tag_at(tags, t64, base);
        int last  = tag_at(tags, t64, base + L - 1);
        float gold = a + startt[first] + endt[last];
        if (mask_nz(mask, mk, base + SS - 1))
            gold += feats[(base + (size_t)(SS - 1)) * TT + last];
        g_partial[BB + b] = -gold;
        // last-block-done protocol
        __threadfence();
        int ticket = atomicAdd(&g_ticket, 1);
        s_last = (ticket == gridDim.x - 1) ? 1 : 0;
    }
    __syncthreads();

    if (s_last) {
        if (tid == 0) g_ticket = 0;            // self-reset for graph replays
        // deterministic fixed-order reduction of all 512 partials
        float v = g_partial[tid];              // tid in [0,512): covers both halves
#pragma unroll
        for (int o = 16; o; o >>= 1) v += __shfl_down_sync(0xffffffffu, v, o);
        if ((tid & 31) == 0) swr[tid >> 5] = v;
        __syncthreads();
        if (tid == 0) {
            float tot = 0.f;
#pragma unroll
            for (int ww = 0; ww < 16; ww++) tot += swr[ww];
            out[0] = tot;
        }
    }
}

extern "C" void kernel_launch(void* const* d_in, const int* in_sizes, int n_in,
                              void* d_out, int out_size) {
    const float* feats  = (const float*)d_in[0];
    const float* trans  = (const float*)d_in[1];
    const float* startt = (const float*)d_in[2];
    const float* endt   = (const float*)d_in[3];
    const void*  tags   = d_in[4];
    const void*  mask   = d_in[5];
    float* out = (float*)d_out;

    crf_fwd_kernel<<<NCTA, 128>>>(feats, trans, startt, endt, mask);
    crf_gold_kernel<<<BB, 512>>>(feats, trans, startt, endt, tags, mask, out);
}